// round 2
// baseline (speedup 1.0000x reference)
#include <cuda_runtime.h>

// Problem constants
#define BB  2
#define CC  512
#define NN  4096   // H*W = 64*64
#define GG  32
#define CGG 16     // channels per group

// Scratch (allocation-free rule: __device__ globals)
__device__ float g_hn  [(size_t)BB * NN * CC];   // groupnorm output, [b, n, c]
__device__ float g_q   [(size_t)BB * NN * CC];   // [b, n, c]
__device__ float g_k   [(size_t)BB * NN * CC];   // [b, n, c]
__device__ float g_v   [(size_t)BB * NN * CC];   // [b, i, c]  (v transposed)
__device__ float g_attn[(size_t)BB * NN * NN];   // [b, i, j]
__device__ float g_h2  [(size_t)BB * NN * CC];   // [b, j, c]  (= h_[c,j] transposed)

// ---------------------------------------------------------------------------
// GroupNorm: stats over (C/32, H, W) per (b, g); write normalized+affine
// result TRANSPOSED to [b, n, c] so all downstream GEMMs are row-major NT.
// ---------------------------------------------------------------------------
__global__ void groupnorm_kernel(const float* __restrict__ x,
                                 const float* __restrict__ gw,
                                 const float* __restrict__ gb)
{
    const int b = blockIdx.x / GG;
    const int g = blockIdx.x % GG;
    const int cbase = g * CGG;
    const int tid = threadIdx.x;   // 256

    const float* xg = x + ((size_t)b * CC + cbase) * NN;

    float s = 0.f, ss = 0.f;
    for (int c = 0; c < CGG; ++c) {
        const float* xc = xg + (size_t)c * NN;
        for (int n = tid; n < NN; n += 256) {
            float v = xc[n];
            s += v; ss += v * v;
        }
    }
    #pragma unroll
    for (int o = 16; o > 0; o >>= 1) {
        s  += __shfl_xor_sync(0xffffffffu, s,  o);
        ss += __shfl_xor_sync(0xffffffffu, ss, o);
    }
    __shared__ float red[16];
    const int wid = tid >> 5, lane = tid & 31;
    if (lane == 0) { red[wid] = s; red[8 + wid] = ss; }
    __syncthreads();
    s  = red[tid & 7];
    ss = red[8 + (tid & 7)];
    #pragma unroll
    for (int o = 4; o > 0; o >>= 1) {
        s  += __shfl_xor_sync(0xffffffffu, s,  o);
        ss += __shfl_xor_sync(0xffffffffu, ss, o);
    }
    const float inv_cnt = 1.f / (float)(CGG * NN);
    const float mean = s * inv_cnt;
    const float var  = ss * inv_cnt - mean * mean;
    const float rstd = rsqrtf(var + 1e-6f);

    // Transposed write via 16x16 shared tile (coalesced-ish both ways)
    const int tx = tid & 15, ty = tid >> 4;
    const float sc = rstd * gw[cbase + ty];
    const float sh = gb[cbase + ty] - mean * sc;
    const float* xrow = x + ((size_t)b * CC + cbase + ty) * NN;
    __shared__ float tile[16][17];
    for (int n0 = 0; n0 < NN; n0 += 16) {
        float v = xrow[n0 + tx];
        __syncthreads();                 // protect tile from previous iter reads
        tile[ty][tx] = v * sc + sh;
        __syncthreads();
        g_hn[((size_t)b * NN + n0 + ty) * CC + cbase + tx] = tile[tx][ty];
    }
}

// ---------------------------------------------------------------------------
// SGEMM NT: C[m,n] = epi( sum_k A[m,k] * B[n,k] )
// 128x128 block, BK=8, 256 threads, 8x8 per thread. All dims multiples of 128/8.
// ---------------------------------------------------------------------------
enum { EPI_NONE = 0, EPI_BIAS_N = 1, EPI_SCALE = 2, EPI_PROJ = 3 };

template <int EPI>
__global__ __launch_bounds__(256, 2)
void gemm_nt_kernel(const float* __restrict__ A, int lda, size_t sA,
                    const float* __restrict__ B, int ldb, size_t sB,
                    float*       __restrict__ C, int ldc, size_t sC,
                    int K,
                    const float* __restrict__ bias,
                    const float* __restrict__ resid, size_t sR,
                    float scale)
{
    A += (size_t)blockIdx.z * sA;
    B += (size_t)blockIdx.z * sB;
    C += (size_t)blockIdx.z * sC;
    if (EPI == EPI_PROJ) resid += (size_t)blockIdx.z * sR;

    __shared__ float As[8][128];
    __shared__ float Bs[8][128];

    const int tid  = threadIdx.x;
    const int lrow = tid >> 1;           // 0..127
    const int lcol = (tid & 1) << 2;     // 0 or 4
    const int tn = tid & 15;
    const int tm = tid >> 4;

    const float* aptr = A + (size_t)(blockIdx.y * 128 + lrow) * lda + lcol;
    const float* bptr = B + (size_t)(blockIdx.x * 128 + lrow) * ldb + lcol;

    float acc[8][8];
    #pragma unroll
    for (int i = 0; i < 8; i++)
        #pragma unroll
        for (int j = 0; j < 8; j++) acc[i][j] = 0.f;

    for (int k0 = 0; k0 < K; k0 += 8) {
        float4 a = *(const float4*)(aptr + k0);
        float4 b = *(const float4*)(bptr + k0);
        __syncthreads();
        As[lcol + 0][lrow] = a.x; As[lcol + 1][lrow] = a.y;
        As[lcol + 2][lrow] = a.z; As[lcol + 3][lrow] = a.w;
        Bs[lcol + 0][lrow] = b.x; Bs[lcol + 1][lrow] = b.y;
        Bs[lcol + 2][lrow] = b.z; Bs[lcol + 3][lrow] = b.w;
        __syncthreads();
        #pragma unroll
        for (int kk = 0; kk < 8; kk++) {
            float af[8], bf[8];
            #pragma unroll
            for (int i = 0; i < 8; i++) af[i] = As[kk][tm * 8 + i];
            #pragma unroll
            for (int j = 0; j < 8; j++) bf[j] = Bs[kk][tn * 8 + j];
            #pragma unroll
            for (int i = 0; i < 8; i++)
                #pragma unroll
                for (int j = 0; j < 8; j++)
                    acc[i][j] = fmaf(af[i], bf[j], acc[i][j]);
        }
    }

    const int row0 = blockIdx.y * 128 + tm * 8;
    const int col0 = blockIdx.x * 128 + tn * 8;

    float bn[8];
    if (EPI == EPI_BIAS_N) {
        #pragma unroll
        for (int j = 0; j < 8; j++) bn[j] = bias[col0 + j];
    }

    #pragma unroll
    for (int i = 0; i < 8; i++) {
        float* crow = C + (size_t)(row0 + i) * ldc + col0;
        float out[8];
        #pragma unroll
        for (int j = 0; j < 8; j++) out[j] = acc[i][j];
        if (EPI == EPI_BIAS_N) {
            #pragma unroll
            for (int j = 0; j < 8; j++) out[j] += bn[j];
        }
        if (EPI == EPI_SCALE) {
            #pragma unroll
            for (int j = 0; j < 8; j++) out[j] *= scale;
        }
        if (EPI == EPI_PROJ) {
            const float bm = bias[row0 + i];
            const float* rrow = resid + (size_t)(row0 + i) * ldc + col0;
            #pragma unroll
            for (int j = 0; j < 8; j++) out[j] += bm + rrow[j];
        }
        *(float4*)(crow)     = make_float4(out[0], out[1], out[2], out[3]);
        *(float4*)(crow + 4) = make_float4(out[4], out[5], out[6], out[7]);
    }
}

// ---------------------------------------------------------------------------
// SGEMM TN: C[m,n] = sum_k A[k,m] * B[k,n]   (both operands k-leading row-major)
// Used for h2[j,c] = sum_i attn[i,j] * v[i,c]
// ---------------------------------------------------------------------------
__global__ __launch_bounds__(256, 2)
void gemm_tn_kernel(const float* __restrict__ A, int lda, size_t sA,
                    const float* __restrict__ B, int ldb, size_t sB,
                    float*       __restrict__ C, int ldc, size_t sC,
                    int K)
{
    A += (size_t)blockIdx.z * sA;
    B += (size_t)blockIdx.z * sB;
    C += (size_t)blockIdx.z * sC;

    __shared__ float As[8][128];
    __shared__ float Bs[8][128];

    const int tid  = threadIdx.x;
    const int krow = tid >> 5;          // 0..7
    const int c4   = (tid & 31) << 2;   // 0..124
    const int tn = tid & 15;
    const int tm = tid >> 4;

    const float* aptr = A + (size_t)krow * lda + blockIdx.y * 128 + c4;
    const float* bptr = B + (size_t)krow * ldb + blockIdx.x * 128 + c4;

    float acc[8][8];
    #pragma unroll
    for (int i = 0; i < 8; i++)
        #pragma unroll
        for (int j = 0; j < 8; j++) acc[i][j] = 0.f;

    for (int k0 = 0; k0 < K; k0 += 8) {
        float4 a = *(const float4*)(aptr + (size_t)k0 * lda);
        float4 b = *(const float4*)(bptr + (size_t)k0 * ldb);
        __syncthreads();
        *(float4*)&As[krow][c4] = a;
        *(float4*)&Bs[krow][c4] = b;
        __syncthreads();
        #pragma unroll
        for (int kk = 0; kk < 8; kk++) {
            float af[8], bf[8];
            #pragma unroll
            for (int i = 0; i < 8; i++) af[i] = As[kk][tm * 8 + i];
            #pragma unroll
            for (int j = 0; j < 8; j++) bf[j] = Bs[kk][tn * 8 + j];
            #pragma unroll
            for (int i = 0; i < 8; i++)
                #pragma unroll
                for (int j = 0; j < 8; j++)
                    acc[i][j] = fmaf(af[i], bf[j], acc[i][j]);
        }
    }

    const int row0 = blockIdx.y * 128 + tm * 8;
    const int col0 = blockIdx.x * 128 + tn * 8;
    #pragma unroll
    for (int i = 0; i < 8; i++) {
        float* crow = C + (size_t)(row0 + i) * ldc + col0;
        *(float4*)(crow)     = make_float4(acc[i][0], acc[i][1], acc[i][2], acc[i][3]);
        *(float4*)(crow + 4) = make_float4(acc[i][4], acc[i][5], acc[i][6], acc[i][7]);
    }
}

// ---------------------------------------------------------------------------
// Row softmax over g_attn: one block per row (4096 elems in registers)
// ---------------------------------------------------------------------------
__global__ void softmax_kernel()
{
    const size_t row = blockIdx.x;
    float* p = g_attn + row * (size_t)NN;
    const int tid = threadIdx.x;  // 256

    float v[16];
    float m = -1e30f;
    #pragma unroll
    for (int r = 0; r < 16; r++) { v[r] = p[tid + 256 * r]; m = fmaxf(m, v[r]); }

    #pragma unroll
    for (int o = 16; o > 0; o >>= 1) m = fmaxf(m, __shfl_xor_sync(0xffffffffu, m, o));
    __shared__ float red[8];
    const int wid = tid >> 5, lane = tid & 31;
    if (lane == 0) red[wid] = m;
    __syncthreads();
    m = red[tid & 7];
    #pragma unroll
    for (int o = 4; o > 0; o >>= 1) m = fmaxf(m, __shfl_xor_sync(0xffffffffu, m, o));

    float s = 0.f;
    #pragma unroll
    for (int r = 0; r < 16; r++) { float e = __expf(v[r] - m); v[r] = e; s += e; }
    #pragma unroll
    for (int o = 16; o > 0; o >>= 1) s += __shfl_xor_sync(0xffffffffu, s, o);
    __syncthreads();
    if (lane == 0) red[wid] = s;
    __syncthreads();
    s = red[tid & 7];
    #pragma unroll
    for (int o = 4; o > 0; o >>= 1) s += __shfl_xor_sync(0xffffffffu, s, o);

    const float inv = 1.f / s;
    #pragma unroll
    for (int r = 0; r < 16; r++) p[tid + 256 * r] = v[r] * inv;
}

// ---------------------------------------------------------------------------
extern "C" void kernel_launch(void* const* d_in, const int* in_sizes, int n_in,
                              void* d_out, int out_size)
{
    const float* x  = (const float*)d_in[0];
    const float* nw = (const float*)d_in[1];
    const float* nb = (const float*)d_in[2];
    const float* wq = (const float*)d_in[3];
    const float* bq = (const float*)d_in[4];
    const float* wk = (const float*)d_in[5];
    const float* bk = (const float*)d_in[6];
    const float* wv = (const float*)d_in[7];
    const float* bv = (const float*)d_in[8];
    const float* wp = (const float*)d_in[9];
    const float* bp = (const float*)d_in[10];
    float* out = (float*)d_out;

    float *hn, *q, *k, *v, *attn, *h2;
    cudaGetSymbolAddress((void**)&hn,   g_hn);
    cudaGetSymbolAddress((void**)&q,    g_q);
    cudaGetSymbolAddress((void**)&k,    g_k);
    cudaGetSymbolAddress((void**)&v,    g_v);
    cudaGetSymbolAddress((void**)&attn, g_attn);
    cudaGetSymbolAddress((void**)&h2,   g_h2);

    const size_t sNC  = (size_t)NN * CC;   // per-batch stride of [n,c] tensors
    const size_t sNN2 = (size_t)NN * NN;   // per-batch stride of attn
    const size_t sCN  = (size_t)CC * NN;   // per-batch stride of [c,n] tensors

    // 1) GroupNorm -> hn [b, n, c]
    groupnorm_kernel<<<BB * GG, 256>>>(x, nw, nb);

    // 2) Q/K/V = hn @ W^T + b   (M = B*N = 8192, N = 512, K = 512)
    gemm_nt_kernel<EPI_BIAS_N><<<dim3(4, 64, 1), 256>>>(hn, CC, 0, wq, CC, 0, q, CC, 0,
                                                        CC, bq, nullptr, 0, 1.f);
    gemm_nt_kernel<EPI_BIAS_N><<<dim3(4, 64, 1), 256>>>(hn, CC, 0, wk, CC, 0, k, CC, 0,
                                                        CC, bk, nullptr, 0, 1.f);
    gemm_nt_kernel<EPI_BIAS_N><<<dim3(4, 64, 1), 256>>>(hn, CC, 0, wv, CC, 0, v, CC, 0,
                                                        CC, bv, nullptr, 0, 1.f);

    // 3) logits[i,j] = scale * q[i,:] . k[j,:]   (per batch 4096x4096x512)
    gemm_nt_kernel<EPI_SCALE><<<dim3(32, 32, 2), 256>>>(q, CC, sNC, k, CC, sNC,
                                                        attn, NN, sNN2,
                                                        CC, nullptr, nullptr, 0,
                                                        0.044194173824159216f); // 512^-0.5

    // 4) softmax over last axis (rows i)
    softmax_kernel<<<BB * NN, 256>>>();

    // 5) h2[j,c] = sum_i attn[i,j] * v[i,c]   (TN, K = 4096)
    gemm_tn_kernel<<<dim3(4, 32, 2), 256>>>(attn, NN, sNN2, v, CC, sNC,
                                            h2, CC, sNC, NN);

    // 6) out[b,o,n] = x + bp[o] + sum_c wp[o,c] * h2[n,c]
    gemm_nt_kernel<EPI_PROJ><<<dim3(32, 4, 2), 256>>>(wp, CC, 0, h2, CC, sNC,
                                                      out, NN, sCN,
                                                      CC, bp, x, sCN, 1.f);
}

// round 4
// speedup vs baseline: 3.1868x; 3.1868x over previous
#include <cuda_runtime.h>
#include <cstdint>

#define BB 2
#define CC 512
#define NN 4096
#define GG 32
#define CGG 16
#define SM_SCALE 0.044194173824159216f

// ---------------- scratch (__device__ globals; allocation-free rule) --------
__device__ float g_hn   [(size_t)BB * NN * CC];   // groupnorm out [b*n, c]
__device__ float g_q    [(size_t)BB * NN * CC];   // [b*n, c]
__device__ float g_k    [(size_t)BB * NN * CC];   // [b*n, c]
__device__ float g_vt   [(size_t)CC * BB * NN];   // [c, b*n]
__device__ float g_attn [(size_t)BB * NN * NN];   // logits [b, i, j]
__device__ float g_attnT[(size_t)BB * NN * NN];   // softmax^T [b, j, i]
__device__ float g_h2   [(size_t)BB * NN * CC];   // [b, j, c]
__device__ float g_rowmax[BB * NN];
__device__ float g_rowinv[BB * NN];

// ---------------------------------------------------------------------------
__device__ __forceinline__ uint32_t smem_u32(const void* p) {
    uint32_t a;
    asm("{ .reg .u64 t; cvta.to.shared.u64 t, %1; cvt.u32.u64 %0, t; }"
        : "=r"(a) : "l"(p));
    return a;
}
__device__ __forceinline__ void cp_async16(uint32_t saddr, const void* g) {
    asm volatile("cp.async.cg.shared.global [%0], [%1], 16;" :: "r"(saddr), "l"(g));
}
__device__ __forceinline__ void mma_tf32(float d[4], const uint32_t a[4], const uint32_t b[2]) {
    asm volatile(
        "mma.sync.aligned.m16n8k8.row.col.f32.tf32.tf32.f32 "
        "{%0,%1,%2,%3}, {%4,%5,%6,%7}, {%8,%9}, {%0,%1,%2,%3};"
        : "+f"(d[0]), "+f"(d[1]), "+f"(d[2]), "+f"(d[3])
        : "r"(a[0]), "r"(a[1]), "r"(a[2]), "r"(a[3]), "r"(b[0]), "r"(b[1]));
}

// ---------------------------------------------------------------------------
// GroupNorm -> g_hn [b*n, c]
// ---------------------------------------------------------------------------
__global__ void groupnorm_kernel(const float* __restrict__ x,
                                 const float* __restrict__ gw,
                                 const float* __restrict__ gb)
{
    const int b = blockIdx.x / GG;
    const int g = blockIdx.x % GG;
    const int cbase = g * CGG;
    const int tid = threadIdx.x;   // 256

    const float* xg = x + ((size_t)b * CC + cbase) * NN;

    float s = 0.f, ss = 0.f;
    for (int c = 0; c < CGG; ++c) {
        const float* xc = xg + (size_t)c * NN;
        for (int n = tid; n < NN; n += 256) {
            float v = xc[n];
            s += v; ss += v * v;
        }
    }
    #pragma unroll
    for (int o = 16; o > 0; o >>= 1) {
        s  += __shfl_xor_sync(0xffffffffu, s,  o);
        ss += __shfl_xor_sync(0xffffffffu, ss, o);
    }
    __shared__ float red[16];
    const int wid = tid >> 5, lane = tid & 31;
    if (lane == 0) { red[wid] = s; red[8 + wid] = ss; }
    __syncthreads();
    s  = red[tid & 7];
    ss = red[8 + (tid & 7)];
    #pragma unroll
    for (int o = 4; o > 0; o >>= 1) {
        s  += __shfl_xor_sync(0xffffffffu, s,  o);
        ss += __shfl_xor_sync(0xffffffffu, ss, o);
    }
    const float inv_cnt = 1.f / (float)(CGG * NN);
    const float mean = s * inv_cnt;
    const float var  = ss * inv_cnt - mean * mean;
    const float rstd = rsqrtf(var + 1e-6f);

    const int tx = tid & 15, ty = tid >> 4;
    const float sc = rstd * gw[cbase + ty];
    const float sh = gb[cbase + ty] - mean * sc;
    const float* xrow = x + ((size_t)b * CC + cbase + ty) * NN;
    __shared__ float tile[16][17];
    for (int n0 = 0; n0 < NN; n0 += 16) {
        float v = xrow[n0 + tx];
        __syncthreads();
        tile[ty][tx] = v * sc + sh;
        __syncthreads();
        g_hn[((size_t)b * NN + n0 + ty) * CC + cbase + tx] = tile[tx][ty];
    }
}

// ---------------------------------------------------------------------------
// tf32 mma.sync NT GEMM: C[m,n] = sum_k A[m,k]*B[n,k]
// CTA 128x128, 128 threads, 4 warps (2x2), warp tile 64x64.
// BK=16, 3-stage cp.async pipeline, smem stride 20 floats (conflict-free).
// EPI: 0 none, 1 +bias[col], 2 +bias[row], 3 +bias[row]+resid
// ---------------------------------------------------------------------------
#define PADK 20
#define SLOT (128 * PADK)                 // floats per stage per operand
#define GEMM_SMEM_BYTES (3 * 2 * SLOT * 4)   // 61440

template <int EPI>
__global__ void __launch_bounds__(128)
gemm_mma(const float* __restrict__ A, int lda, size_t sA,
         const float* __restrict__ B, int ldb, size_t sB,
         float*       __restrict__ C, int ldc, size_t sC,
         int K,
         const float* __restrict__ bias,
         const float* __restrict__ resid, size_t sR)
{
    extern __shared__ float smem[];                 // As[3][SLOT] | Bs[3][SLOT]
    const uint32_t sb_a = smem_u32(smem);
    const uint32_t sb_b = sb_a + 3 * SLOT * 4;
    const uint32_t* __restrict__ Asu = (const uint32_t*)smem;
    const uint32_t* __restrict__ Bsu = (const uint32_t*)smem + 3 * SLOT;

    const int tid  = threadIdx.x;
    const int lane = tid & 31;
    const int wid  = tid >> 5;
    const int r    = lane >> 2;
    const int cq   = lane & 3;
    const int m_base = (wid & 1) * 64;
    const int n_base = (wid >> 1) * 64;

    A += (size_t)blockIdx.z * sA;
    B += (size_t)blockIdx.z * sB;
    C += (size_t)blockIdx.z * sC;
    if (EPI == 3) resid += (size_t)blockIdx.z * sR;

    const int m0 = blockIdx.y * 128;
    const int n0 = blockIdx.x * 128;
    const float* Ap = A + (size_t)m0 * lda;
    const float* Bp = B + (size_t)n0 * ldb;

    const int nk = K >> 4;

    // stage loader: 128 rows x 16 cols per operand, 4 float4 per thread each
    auto issue = [&](int chunk) {
        const int st = chunk % 3;
        #pragma unroll
        for (int u = 0; u < 4; u++) {
            const int lin = u * 128 + tid;
            const int row = lin >> 2;
            const int c4  = (lin & 3) << 2;
            const uint32_t so = (uint32_t)(st * SLOT + row * PADK + c4) * 4;
            cp_async16(sb_a + so, Ap + (size_t)row * lda + chunk * 16 + c4);
            cp_async16(sb_b + so, Bp + (size_t)row * ldb + chunk * 16 + c4);
        }
        asm volatile("cp.async.commit_group;" ::: "memory");
    };

    issue(0);
    issue(1);

    float acc[4][8][4];
    #pragma unroll
    for (int i = 0; i < 4; i++)
        #pragma unroll
        for (int j = 0; j < 8; j++)
            #pragma unroll
            for (int t = 0; t < 4; t++) acc[i][j][t] = 0.f;

    for (int c = 0; c < nk; c++) {
        asm volatile("cp.async.wait_group 1;" ::: "memory");
        __syncthreads();
        if (c + 2 < nk) issue(c + 2);

        const int buf = (c % 3) * SLOT;
        #pragma unroll
        for (int kk = 0; kk < 16; kk += 8) {
            uint32_t a[4][4], b[8][2];
            #pragma unroll
            for (int i = 0; i < 4; i++) {
                const int rowo = buf + (m_base + i * 16 + r) * PADK + kk + cq;
                a[i][0] = Asu[rowo];
                a[i][1] = Asu[rowo + 8 * PADK];
                a[i][2] = Asu[rowo + 4];
                a[i][3] = Asu[rowo + 8 * PADK + 4];
            }
            #pragma unroll
            for (int j = 0; j < 8; j++) {
                const int rowo = buf + (n_base + j * 8 + r) * PADK + kk + cq;
                b[j][0] = Bsu[rowo];
                b[j][1] = Bsu[rowo + 4];
            }
            #pragma unroll
            for (int i = 0; i < 4; i++)
                #pragma unroll
                for (int j = 0; j < 8; j++)
                    mma_tf32(acc[i][j], a[i], b[j]);
        }
    }

    // Epilogue: m16n8 fragment layout -> float2 stores
    #pragma unroll
    for (int i = 0; i < 4; i++) {
        const int row = m0 + m_base + i * 16 + r;
        float brow0 = 0.f, brow1 = 0.f;
        if (EPI == 2 || EPI == 3) { brow0 = bias[row]; brow1 = bias[row + 8]; }
        #pragma unroll
        for (int j = 0; j < 8; j++) {
            const int col = n0 + n_base + j * 8 + cq * 2;
            float v0 = acc[i][j][0], v1 = acc[i][j][1];
            float v2 = acc[i][j][2], v3 = acc[i][j][3];
            if (EPI == 1) {
                const float bc0 = bias[col], bc1 = bias[col + 1];
                v0 += bc0; v1 += bc1; v2 += bc0; v3 += bc1;
            }
            if (EPI == 2 || EPI == 3) { v0 += brow0; v1 += brow0; v2 += brow1; v3 += brow1; }
            if (EPI == 3) {
                const float2 r0 = *(const float2*)(resid + (size_t)row * ldc + col);
                const float2 r1 = *(const float2*)(resid + (size_t)(row + 8) * ldc + col);
                v0 += r0.x; v1 += r0.y; v2 += r1.x; v3 += r1.y;
            }
            *(float2*)(C + (size_t)row * ldc + col)       = make_float2(v0, v1);
            *(float2*)(C + (size_t)(row + 8) * ldc + col) = make_float2(v2, v3);
        }
    }
}

// ---------------------------------------------------------------------------
// Softmax pass 1: per-row max and 1/sum(exp(scale*(v-m)))
// ---------------------------------------------------------------------------
__global__ void rowstat_kernel()
{
    const size_t row = blockIdx.x;
    const float* p = g_attn + row * (size_t)NN;
    const int tid = threadIdx.x;  // 256

    float v[16];
    float m = -1e30f;
    #pragma unroll
    for (int r = 0; r < 16; r++) { v[r] = p[tid + 256 * r]; m = fmaxf(m, v[r]); }

    #pragma unroll
    for (int o = 16; o > 0; o >>= 1) m = fmaxf(m, __shfl_xor_sync(0xffffffffu, m, o));
    __shared__ float red[8];
    const int wid = tid >> 5, lane = tid & 31;
    if (lane == 0) red[wid] = m;
    __syncthreads();
    m = red[tid & 7];
    #pragma unroll
    for (int o = 4; o > 0; o >>= 1) m = fmaxf(m, __shfl_xor_sync(0xffffffffu, m, o));

    float s = 0.f;
    #pragma unroll
    for (int r = 0; r < 16; r++) s += __expf(SM_SCALE * (v[r] - m));
    #pragma unroll
    for (int o = 16; o > 0; o >>= 1) s += __shfl_xor_sync(0xffffffffu, s, o);
    __syncthreads();
    if (lane == 0) red[wid] = s;
    __syncthreads();
    s = red[tid & 7];
    #pragma unroll
    for (int o = 4; o > 0; o >>= 1) s += __shfl_xor_sync(0xffffffffu, s, o);

    if (tid == 0) { g_rowmax[row] = m; g_rowinv[row] = 1.f / s; }
}

// ---------------------------------------------------------------------------
// Softmax pass 2: p = exp(scale*(v - m)) * inv, written TRANSPOSED to attnT
// ---------------------------------------------------------------------------
__global__ void softmax_tr_kernel()
{
    __shared__ float t[32][33];
    const int b  = blockIdx.z;
    const int j0 = blockIdx.x * 32;
    const int i0 = blockIdx.y * 32;
    const float* src = g_attn  + (size_t)b * NN * NN;
    float*       dst = g_attnT + (size_t)b * NN * NN;
    const int tx = threadIdx.x, ty = threadIdx.y;   // (32, 8)

    #pragma unroll
    for (int r = 0; r < 4; r++) {
        const int i = i0 + ty + 8 * r;
        const float v = src[(size_t)i * NN + j0 + tx];
        t[ty + 8 * r][tx] = __expf(SM_SCALE * (v - g_rowmax[b * NN + i])) * g_rowinv[b * NN + i];
    }
    __syncthreads();
    #pragma unroll
    for (int r = 0; r < 4; r++) {
        const int j = j0 + ty + 8 * r;
        dst[(size_t)j * NN + i0 + tx] = t[tx][ty + 8 * r];
    }
}

// ---------------------------------------------------------------------------
extern "C" void kernel_launch(void* const* d_in, const int* in_sizes, int n_in,
                              void* d_out, int out_size)
{
    const float* x  = (const float*)d_in[0];
    const float* nw = (const float*)d_in[1];
    const float* nb = (const float*)d_in[2];
    const float* wq = (const float*)d_in[3];
    const float* bq = (const float*)d_in[4];
    const float* wk = (const float*)d_in[5];
    const float* bk = (const float*)d_in[6];
    const float* wv = (const float*)d_in[7];
    const float* bv = (const float*)d_in[8];
    const float* wp = (const float*)d_in[9];
    const float* bp = (const float*)d_in[10];
    float* out = (float*)d_out;

    float *hn, *q, *k, *vt, *attn, *attnT, *h2;
    cudaGetSymbolAddress((void**)&hn,    g_hn);
    cudaGetSymbolAddress((void**)&q,     g_q);
    cudaGetSymbolAddress((void**)&k,     g_k);
    cudaGetSymbolAddress((void**)&vt,    g_vt);
    cudaGetSymbolAddress((void**)&attn,  g_attn);
    cudaGetSymbolAddress((void**)&attnT, g_attnT);
    cudaGetSymbolAddress((void**)&h2,    g_h2);

    cudaFuncSetAttribute(gemm_mma<0>, cudaFuncAttributeMaxDynamicSharedMemorySize, GEMM_SMEM_BYTES);
    cudaFuncSetAttribute(gemm_mma<1>, cudaFuncAttributeMaxDynamicSharedMemorySize, GEMM_SMEM_BYTES);
    cudaFuncSetAttribute(gemm_mma<2>, cudaFuncAttributeMaxDynamicSharedMemorySize, GEMM_SMEM_BYTES);
    cudaFuncSetAttribute(gemm_mma<3>, cudaFuncAttributeMaxDynamicSharedMemorySize, GEMM_SMEM_BYTES);

    const size_t sNC  = (size_t)NN * CC;
    const size_t sNN2 = (size_t)NN * NN;
    const size_t sCN  = (size_t)CC * NN;

    // 1) GroupNorm
    groupnorm_kernel<<<BB * GG, 256>>>(x, nw, nb);

    // 2) q[i,c] = hn[i,:]·wq[c,:] + bq[c]     M=8192 N=512 K=512
    gemm_mma<1><<<dim3(4, 64, 1), 128, GEMM_SMEM_BYTES>>>(hn, CC, 0, wq, CC, 0,
                                                          q, CC, 0, CC, bq, nullptr, 0);
    gemm_mma<1><<<dim3(4, 64, 1), 128, GEMM_SMEM_BYTES>>>(hn, CC, 0, wk, CC, 0,
                                                          k, CC, 0, CC, bk, nullptr, 0);
    //    vt[c, b*N+i] = wv[c,:]·hn[i,:] + bv[c]   M=512 N=8192 K=512
    gemm_mma<2><<<dim3(64, 4, 1), 128, GEMM_SMEM_BYTES>>>(wv, CC, 0, hn, CC, 0,
                                                          vt, BB * NN, 0, CC, bv, nullptr, 0);

    // 3) logits[i,j] = q[i,:]·k[j,:]   per batch 4096x4096x512
    gemm_mma<0><<<dim3(32, 32, 2), 128, GEMM_SMEM_BYTES>>>(q, CC, sNC, k, CC, sNC,
                                                           attn, NN, sNN2, CC,
                                                           nullptr, nullptr, 0);

    // 4) softmax over j (scale folded), transposed output attnT[j,i]
    rowstat_kernel<<<BB * NN, 256>>>();
    softmax_tr_kernel<<<dim3(NN / 32, NN / 32, BB), dim3(32, 8)>>>();

    // 5) h2[j,c] = sum_i attnT[j,i] * vt[c, b*N+i]   M=4096 N=512 K=4096
    gemm_mma<0><<<dim3(4, 32, 2), 128, GEMM_SMEM_BYTES>>>(attnT, NN, sNN2,
                                                          vt, BB * NN, (size_t)NN,
                                                          h2, CC, sNC, NN,
                                                          nullptr, nullptr, 0);

    // 6) out[o,j] = x + bp[o] + sum_c wp[o,c]*h2[j,c]   M=512 N=4096 K=512
    gemm_mma<3><<<dim3(32, 4, 2), 128, GEMM_SMEM_BYTES>>>(wp, CC, 0, h2, CC, sNC,
                                                          out, NN, sCN, CC,
                                                          bp, x, sCN);
}